// round 16
// baseline (speedup 1.0000x reference)
#include <cuda_runtime.h>
#include <cuda_fp16.h>
#include <cstdint>

// B=64, T=4096, D=64. Token tile 62 (+2 halo rows) -> M=64 = 4 m16-tiles, ZERO
// padding. Grid 64 x 67 = 4288 CTAs (last tile ragged: 4 tokens).
// 320 threads = 10 warps, 3 CTAs/SM (smem 69120 B, launch_bounds(320,3)).
// GEMMs: mma.sync m16n8k16 fp16 (fp32 accum). A operands in packed-half2 fragment
// layout. B fragments pre-converted to fp16 fragment order by a prep kernel.
// Activations via MUFU.TANH: sigm = 0.5*tanh(z/2)+0.5.
#define TT 62              // tokens per CTA tile
#define NT 67              // tiles per batch row (ceil(4096/62))
#define TSLOTW 528         // words (b32) per m16 tile: 4 chunks x 132
#define PST 68             // preactivation row stride (elements)

// shared memory byte offsets (params stay in global — L1-resident)
#define OFF_XF   0                  // 8448 B (x, fp16 frags, 4 tiles)
#define OFF_HF   8448               // 8448 B (h / delta-norm, fp16 frags)
#define OFF_BP   16896              // 17408 B (b-linear preact, fp32, 64 rows)
#define OFF_QKVA 34304              // 34816 B (4 x 64x68 fp16 preacts)
#define SMEM_BYTES 69120

// pre-converted weight fragments: [mat 0..5][n16 0..3][cg 0..3][lane 0..31]
__device__ uint4 g_wfrag[6 * 4 * 4 * 32];

// hardware tanh (MUFU.TANH, sm_75+); max err ~2e-5 << fp16 GEMM error floor
__device__ __forceinline__ float tanh_hw(float a) {
    float t;
    asm("tanh.approx.f32 %0, %1;" : "=f"(t) : "f"(a));
    return t;
}
__device__ __forceinline__ float sigm(float z) {
    return fmaf(0.5f, tanh_hw(0.5f * z), 0.5f);
}

// interleaved 2-value butterfly reduction (one latency chain for two sums)
__device__ __forceinline__ void wredsum2(float& a, float& b) {
#pragma unroll
    for (int o = 16; o; o >>= 1) {
        a += __shfl_xor_sync(0xffffffffu, a, o);
        b += __shfl_xor_sync(0xffffffffu, b, o);
    }
}

__device__ __forceinline__ unsigned packh2(float lo, float hi) {
    __half2 h = __floats2half2_rn(lo, hi);
    return *(unsigned*)&h;
}

// store packed half2 for adjacent cols (2*lane, 2*lane+1) at row bits gd/hi
__device__ __forceinline__ void frag_store_w(float* tile, int gd, int hi, int lane, unsigned w) {
    const int c = 2 * lane;
    const int cc = c & 15;
    const int word = (c >> 4) * 132 + (4 * gd + ((cc & 7) >> 1)) * 4 + hi + 2 * (cc >> 3);
    ((unsigned*)tile)[word] = w;
}

__device__ __forceinline__ void mma16(float* d, unsigned a0, unsigned a1, unsigned a2, unsigned a3,
                                      unsigned b0, unsigned b1) {
    asm("mma.sync.aligned.m16n8k16.row.col.f32.f16.f16.f32 "
        "{%0,%1,%2,%3}, {%4,%5,%6,%7}, {%8,%9}, {%0,%1,%2,%3};"
        : "+f"(d[0]), "+f"(d[1]), "+f"(d[2]), "+f"(d[3])
        : "r"(a0), "r"(a1), "r"(a2), "r"(a3), "r"(b0), "r"(b1));
}

// Load k64 x n16 pre-converted B-fragments: 4 coalesced LDG.128.
__device__ __forceinline__ void load_bfrag_pre(int mat, int n16, int lane,
                                               unsigned Bf[4][2][2]) {
    const uint4* src = g_wfrag + ((mat * 4 + n16) * 4) * 32;
#pragma unroll
    for (int cg = 0; cg < 4; ++cg) {
        const uint4 v = __ldg(src + cg * 32 + lane);
        Bf[cg][0][0] = v.x;
        Bf[cg][0][1] = v.y;
        Bf[cg][1][0] = v.z;
        Bf[cg][1][1] = v.w;
    }
}

// ---- prep kernel: convert 6 weight matrices into fp16 fragment order ----
__global__ void prep_kernel(const float* __restrict__ qw, const float* __restrict__ kw,
                            const float* __restrict__ vw, const float* __restrict__ aw,
                            const float* __restrict__ bw, const float* __restrict__ pw)
{
    const int idx = blockIdx.x * blockDim.x + threadIdx.x;   // 0..3071
    if (idx >= 6 * 4 * 4 * 32) return;
    const int lane = idx & 31;
    const int cg   = (idx >> 5) & 3;
    const int n16  = (idx >> 7) & 3;
    const int mat  = idx >> 9;
    const float* W = (mat == 0) ? qw : (mat == 1) ? kw : (mat == 2) ? vw
                   : (mat == 3) ? aw : (mat == 4) ? bw : pw;
    const int g = lane >> 2, tg = lane & 3, n0 = n16 * 16;
    const float* r0 = W + (n0 + g) * 64 + 2 * tg + 16 * cg;
    const float* r1 = W + (n0 + g + 8) * 64 + 2 * tg + 16 * cg;
    uint4 v;
    v.x = packh2(r0[0], r0[1]);
    v.y = packh2(r0[8], r0[9]);
    v.z = packh2(r1[0], r1[1]);
    v.w = packh2(r1[8], r1[9]);
    g_wfrag[idx] = v;
}

__global__ void __launch_bounds__(320, 3) gdn_kernel(
    const float* __restrict__ x,   const float* __restrict__ norm_g,
    const float* __restrict__ qb,  const float* __restrict__ kb,
    const float* __restrict__ vb,  const float* __restrict__ ab,
    const float* __restrict__ bb,  const float* __restrict__ pb,
    const float* __restrict__ qcw, const float* __restrict__ qcb,
    const float* __restrict__ kcw, const float* __restrict__ kcb,
    const float* __restrict__ vcw, const float* __restrict__ vcb,
    const float* __restrict__ png, float* __restrict__ out)
{
    extern __shared__ char smc[];
    float* XF   = (float*)(smc + OFF_XF);
    float* HF   = (float*)(smc + OFF_HF);
    float* BPf  = (float*)(smc + OFF_BP);
    __half* QKVA = (__half*)(smc + OFF_QKVA);

    const int tid  = threadIdx.x;
    const int warp = tid >> 5;
    const int lane = tid & 31;
    const int g    = lane >> 2;
    const int tg   = lane & 3;
    const int b    = blockIdx.x / NT;
    const int tile = blockIdx.x - b * NT;
    const int t0   = tile * TT;
    const long xrow0 = (long)b * 4096;       // token row base for this batch

    // ---- x load + zc_rmsnorm -> XF/HF fp16 frags; channels (2*lane, 2*lane+1) ----
    // row r (0..63) <-> global token gt = t0-1+r
    {
        const float2 ng2 = *(const float2*)(norm_g + 2 * lane);
        for (int r = warp; r < 64; r += 10) {
            const int gt = t0 - 1 + r;
            const bool valid = ((unsigned)gt < 4096u);
            float a = 0.f, bv = 0.f;
            if (valid) {
                const float2 xv = *(const float2*)(x + (xrow0 + gt) * 64 + 2 * lane);
                a = xv.x; bv = xv.y;
            }
            const int mt = r >> 4, gd = r & 7, hi = (r >> 3) & 1;
            frag_store_w(XF + mt * TSLOTW, gd, hi, lane, packh2(a, bv));
            float s1 = a + bv, s2 = a * a + bv * bv;
            wredsum2(s1, s2);
            const float mean = s1 * (1.0f / 64.0f);
            const float var  = s2 * (1.0f / 64.0f) - mean * mean;
            const float inv  = rsqrtf(var + 1e-8f);
            frag_store_w(HF + mt * TSLOTW, gd, hi, lane,
                         packh2((a - mean) * inv * ng2.x, (bv - mean) * inv * ng2.y));
        }
    }
    __syncthreads();

    // ---- phase-1: 20 jobs = (matrix 0..4) x (n16 chunk 0..3); 2 jobs/warp ----
    {
        const float* bsrc[5] = { qb, kb, vb, ab, bb };
#pragma unroll
        for (int jj = 0; jj < 2; ++jj) {
            const int job = warp + 10 * jj;
            const int mat = job >> 2;          // 0..4
            const int n16 = job & 3;
            const int n0  = n16 * 16;
            const float* AF = (mat < 3) ? HF : XF;

            unsigned Bf[4][2][2];
            load_bfrag_pre(mat, n16, lane, Bf);

            float bA[2][2];
#pragma unroll
            for (int nn = 0; nn < 2; ++nn) {
                const float2 bv2 = *(const float2*)(bsrc[mat] + n0 + nn * 8 + 2 * tg);
                bA[nn][0] = bv2.x; bA[nn][1] = bv2.y;
            }

            const bool qkv = (mat < 3);
            __half* Ob = QKVA + mat * (64 * PST);   // valid for mat<4

#pragma unroll
            for (int mt = 0; mt < 4; ++mt) {
                const float4* Afp = (const float4*)(AF + mt * TSLOTW);
                float acc[2][4];
#pragma unroll
                for (int i = 0; i < 2; ++i)
#pragma unroll
                    for (int j = 0; j < 4; ++j) acc[i][j] = 0.f;

#pragma unroll
                for (int c = 0; c < 4; ++c) {
                    const float4 av = Afp[c * 33 + lane];
                    const unsigned a0 = __float_as_uint(av.x);
                    const unsigned a1 = __float_as_uint(av.y);
                    const unsigned a2 = __float_as_uint(av.z);
                    const unsigned a3 = __float_as_uint(av.w);
                    mma16(acc[0], a0, a1, a2, a3, Bf[c][0][0], Bf[c][0][1]);
                    mma16(acc[1], a0, a1, a2, a3, Bf[c][1][0], Bf[c][1][1]);
                }
                const int rA = mt * 16 + g, rB = rA + 8;
#pragma unroll
                for (int nn = 0; nn < 2; ++nn) {
                    const int c0 = n0 + nn * 8 + 2 * tg;
#pragma unroll
                    for (int rr = 0; rr < 2; ++rr) {
                        const int r = rr ? rB : rA;
                        const int gt = t0 - 1 + r;
                        float v0 = acc[nn][2 * rr + 0] + bA[nn][0];
                        float v1 = acc[nn][2 * rr + 1] + bA[nn][1];
                        // conv zero-padding: q/k/v preact rows for out-of-range tokens are 0
                        if (qkv && ((unsigned)gt >= 4096u)) { v0 = 0.f; v1 = 0.f; }
                        if (mat < 4) {
                            *(__half2*)(Ob + r * PST + c0) = __floats2half2_rn(v0, v1);
                        } else {
                            *(float2*)(BPf + r * PST + c0) = make_float2(v0, v1);
                        }
                    }
                }
            }
        }
    }
    __syncthreads();

    // ---- per-token stage; channels (2*lane, 2*lane+1), register-carried stencil ----
    // 62 tokens: warps 0..1: 7 from s=1+7w; warps 2..9: 6 from s=15+6(w-2)
    {
        const __half* QP = QKVA;
        const __half* KP = QKVA + 64 * PST;
        const __half* VP = QKVA + 2 * 64 * PST;
        const __half* AP = QKVA + 3 * 64 * PST;
        const int s   = (warp < 2) ? (1 + 7 * warp) : (15 + 6 * (warp - 2));
        const int cnt = (warp < 2) ? 7 : 6;
        const int cc0 = 2 * lane;

        // conv params from global (once per warp)
        float cwq[3][2], cwk[3][2], cwv[3][2];
#pragma unroll
        for (int tap = 0; tap < 3; ++tap) {
            cwq[tap][0] = qcw[cc0 * 3 + tap];  cwq[tap][1] = qcw[(cc0 + 1) * 3 + tap];
            cwk[tap][0] = kcw[cc0 * 3 + tap];  cwk[tap][1] = kcw[(cc0 + 1) * 3 + tap];
            cwv[tap][0] = vcw[cc0 * 3 + tap];  cwv[tap][1] = vcw[(cc0 + 1) * 3 + tap];
        }
        const float2 cbq = *(const float2*)(qcb + cc0);
        const float2 cbk = *(const float2*)(kcb + cc0);
        const float2 cbv = *(const float2*)(vcb + cc0);
        const float2 pg2 = *(const float2*)(png + cc0);

        float qm[2], q0[2], km[2], k0[2], vm[2], v0[2];
        {
            const float2 qa = __half22float2(*(const __half2*)(QP + (s - 1) * PST + cc0));
            const float2 qbv = __half22float2(*(const __half2*)(QP + s * PST + cc0));
            const float2 ka = __half22float2(*(const __half2*)(KP + (s - 1) * PST + cc0));
            const float2 kbv = __half22float2(*(const __half2*)(KP + s * PST + cc0));
            const float2 va = __half22float2(*(const __half2*)(VP + (s - 1) * PST + cc0));
            const float2 vbv = __half22float2(*(const __half2*)(VP + s * PST + cc0));
            qm[0] = qa.x; qm[1] = qa.y; q0[0] = qbv.x; q0[1] = qbv.y;
            km[0] = ka.x; km[1] = ka.y; k0[0] = kbv.x; k0[1] = kbv.y;
            vm[0] = va.x; vm[1] = va.y; v0[0] = vbv.x; v0[1] = vbv.y;
        }

        for (int t = s; t < s + cnt; ++t) {
            if (t0 + t - 1 >= 4096) break;    // ragged last tile
            const float2 qpv = __half22float2(*(const __half2*)(QP + (t + 1) * PST + cc0));
            const float2 kpv = __half22float2(*(const __half2*)(KP + (t + 1) * PST + cc0));
            const float2 vpv = __half22float2(*(const __half2*)(VP + (t + 1) * PST + cc0));
            const float qp[2] = { qpv.x, qpv.y };
            const float kp[2] = { kpv.x, kpv.y };
            const float vp[2] = { vpv.x, vpv.y };
            float qv[2], kv[2], vv[2];
#pragma unroll
            for (int h = 0; h < 2; ++h) {
                qv[h] = sigm(cwq[0][h] * qm[h] + cwq[1][h] * q0[h] + cwq[2][h] * qp[h] + (h ? cbq.y : cbq.x));
                kv[h] = sigm(cwk[0][h] * km[h] + cwk[1][h] * k0[h] + cwk[2][h] * kp[h] + (h ? cbk.y : cbk.x));
                vv[h] = sigm(cwv[0][h] * vm[h] + cwv[1][h] * v0[h] + cwv[2][h] * vp[h] + (h ? cbv.y : cbv.x));
            }
            float qs = qv[0] * qv[0] + qv[1] * qv[1];
            float ks = kv[0] * kv[0] + kv[1] * kv[1];
            wredsum2(qs, ks);
            const float qi = rsqrtf(qs + 1e-8f);
            const float ki = rsqrtf(ks + 1e-8f);
            const float2 av2 = __half22float2(*(const __half2*)(AP + t * PST + cc0));
            const float2 bp2 = *(const float2*)(BPf + t * PST + cc0);
            float d2[2];
            d2[0] = tanh_hw(av2.x) * ((qv[0] * qi) * ((kv[0] * ki) * vv[0])) + bp2.x;
            d2[1] = tanh_hw(av2.y) * ((qv[1] * qi) * ((kv[1] * ki) * vv[1])) + bp2.y;
            float s1 = d2[0] + d2[1], s2 = d2[0] * d2[0] + d2[1] * d2[1];
            wredsum2(s1, s2);
            const float mean = s1 * (1.0f / 64.0f);
            const float var  = s2 * (1.0f / 64.0f) - mean * mean;
            const float inv  = rsqrtf(var + 1e-8f);
            const int tk = t - 1;                 // HF row <-> global token t0+tk
            const int mt = tk >> 4, gd = tk & 7, hi = (tk >> 3) & 1;
            frag_store_w(HF + mt * TSLOTW, gd, hi, lane,
                         packh2((d2[0] - mean) * inv * pg2.x, (d2[1] - mean) * inv * pg2.y));
#pragma unroll
            for (int h = 0; h < 2; ++h) {
                qm[h] = q0[h]; q0[h] = qp[h];
                km[h] = k0[h]; k0[h] = kp[h];
                vm[h] = v0[h]; v0[h] = vp[h];
            }
        }
    }
    __syncthreads();

    // ---- final GEMM: 16 jobs m16 x n16 x k64; warps 0..5 do 2 jobs, 6..9 one ----
    for (int job = warp; job < 16; job += 10) {
        const int mt = job >> 2;
        const int n16 = job & 3;
        const int n0 = n16 * 16;

        unsigned Bf[4][2][2];
        load_bfrag_pre(5, n16, lane, Bf);

        const float4* Afp = (const float4*)(HF + mt * TSLOTW);
        float acc[2][4];
#pragma unroll
        for (int i = 0; i < 2; ++i)
#pragma unroll
            for (int j = 0; j < 4; ++j) acc[i][j] = 0.f;

#pragma unroll
        for (int c = 0; c < 4; ++c) {
            const float4 av = Afp[c * 33 + lane];
            mma16(acc[0], __float_as_uint(av.x), __float_as_uint(av.y),
                  __float_as_uint(av.z), __float_as_uint(av.w),
                  Bf[c][0][0], Bf[c][0][1]);
            mma16(acc[1], __float_as_uint(av.x), __float_as_uint(av.y),
                  __float_as_uint(av.z), __float_as_uint(av.w),
                  Bf[c][1][0], Bf[c][1][1]);
        }
#pragma unroll
        for (int nn = 0; nn < 2; ++nn) {
            const int col = n0 + nn * 8 + 2 * tg;
            const float2 pb2 = *(const float2*)(pb + col);
#pragma unroll
            for (int h = 0; h < 2; ++h) {
                const int row = mt * 16 + g + 8 * h;     // global token t0 + row
                if (row >= TT || t0 + row >= 4096) continue;
                const float d0 = acc[nn][2 * h + 0] + pb2.x;
                const float d1 = acc[nn][2 * h + 1] + pb2.y;
                const float g0 = sigm(d0 * sigm(d0));
                const float g1 = sigm(d1 * sigm(d1));
                const long off = (xrow0 + t0 + row) * 64 + col;
                const float2 xv = *(const float2*)(x + off);
                float2 o = make_float2(xv.x + g0 * d0, xv.y + g1 * d1);
                *(float2*)(out + off) = o;
            }
        }
    }
}

extern "C" void kernel_launch(void* const* d_in, const int* in_sizes, int n_in,
                              void* d_out, int out_size)
{
    const float* x      = (const float*)d_in[0];
    const float* norm_g = (const float*)d_in[1];
    const float* qw  = (const float*)d_in[2];
    const float* qb  = (const float*)d_in[3];
    const float* kw  = (const float*)d_in[4];
    const float* kb  = (const float*)d_in[5];
    const float* vw  = (const float*)d_in[6];
    const float* vb  = (const float*)d_in[7];
    const float* qcw = (const float*)d_in[8];
    const float* qcb = (const float*)d_in[9];
    const float* kcw = (const float*)d_in[10];
    const float* kcb = (const float*)d_in[11];
    const float* vcw = (const float*)d_in[12];
    const float* vcb = (const float*)d_in[13];
    const float* aw  = (const float*)d_in[14];
    const float* ab  = (const float*)d_in[15];
    const float* bw  = (const float*)d_in[16];
    const float* bb  = (const float*)d_in[17];
    const float* png = (const float*)d_in[18];
    const float* pw  = (const float*)d_in[19];
    const float* pb  = (const float*)d_in[20];
    float* out = (float*)d_out;

    prep_kernel<<<6, 512>>>(qw, kw, vw, aw, bw, pw);

    cudaFuncSetAttribute(gdn_kernel, cudaFuncAttributeMaxDynamicSharedMemorySize, SMEM_BYTES);
    gdn_kernel<<<64 * NT, 320, SMEM_BYTES>>>(
        x, norm_g, qb, kb, vb, ab, bb, pb,
        qcw, qcb, kcw, kcb, vcw, vcb, png, out);
}

// round 17
// speedup vs baseline: 1.1566x; 1.1566x over previous
#include <cuda_runtime.h>
#include <cuda_fp16.h>
#include <cstdint>

// B=64, T=4096, D=64. Token tile 64 (+2 halo rows), M padded to 80 (5 m16-tiles).
// 320 threads = 10 warps, 3 CTAs/SM (smem 74976 B, launch_bounds(320,3)).
// GEMMs: mma.sync m16n8k16 fp16 (fp32 accum). A operands in packed-half2 fragment
// layout. B fragments pre-converted to fp16 fragment order by a prep kernel.
// Activations via MUFU.TANH: sigm = 0.5*tanh(z/2)+0.5.
// Norm phase: half-warp reduction (16 lanes x 4 ch, 2 rows/warp-iter, 4-level bfly);
// padding rows 66..79 skip reductions.
#define TSLOTW 528         // words (b32) per m16 tile: 4 chunks x 132
#define PST 68             // preactivation row stride (elements)

// shared memory byte offsets (params stay in global — L1-resident)
#define OFF_XF   0                  // 10560 B (x, fp16 frags)
#define OFF_HF   10560              // 10560 B (h / delta-norm, fp16 frags)
#define OFF_BP   21120              // 17952 B (b-linear preact, fp32)
#define OFF_QKVA 39072              // 35904 B (4 x 66x68 fp16 preacts)
#define SMEM_BYTES 74976

// pre-converted weight fragments: [mat 0..5][n16 0..3][cg 0..3][lane 0..31]
__device__ uint4 g_wfrag[6 * 4 * 4 * 32];

// hardware tanh (MUFU.TANH, sm_75+); max err ~2e-5 << fp16 GEMM error floor
__device__ __forceinline__ float tanh_hw(float a) {
    float t;
    asm("tanh.approx.f32 %0, %1;" : "=f"(t) : "f"(a));
    return t;
}
__device__ __forceinline__ float sigm(float z) {
    return fmaf(0.5f, tanh_hw(0.5f * z), 0.5f);
}

// interleaved 2-value butterfly reduction over full warp (5 levels)
__device__ __forceinline__ void wredsum2(float& a, float& b) {
#pragma unroll
    for (int o = 16; o; o >>= 1) {
        a += __shfl_xor_sync(0xffffffffu, a, o);
        b += __shfl_xor_sync(0xffffffffu, b, o);
    }
}

// 2-value butterfly over 16-lane groups (4 levels); serves both half-warps at once
__device__ __forceinline__ void bfly16_2(float& a, float& b) {
#pragma unroll
    for (int o = 8; o; o >>= 1) {
        a += __shfl_xor_sync(0xffffffffu, a, o);
        b += __shfl_xor_sync(0xffffffffu, b, o);
    }
}

__device__ __forceinline__ unsigned packh2(float lo, float hi) {
    __half2 h = __floats2half2_rn(lo, hi);
    return *(unsigned*)&h;
}

// fragment word index for channel pair (c, c+1), c even, at row bits gd/hi
__device__ __forceinline__ int frag_word(int gd, int hi, int c) {
    const int cc = c & 15;
    return (c >> 4) * 132 + (4 * gd + ((cc & 7) >> 1)) * 4 + hi + 2 * (cc >> 3);
}

// store packed half2 for adjacent cols (2*lane, 2*lane+1) at row bits gd/hi
__device__ __forceinline__ void frag_store_w(float* tile, int gd, int hi, int lane, unsigned w) {
    ((unsigned*)tile)[frag_word(gd, hi, 2 * lane)] = w;
}

__device__ __forceinline__ void mma16(float* d, unsigned a0, unsigned a1, unsigned a2, unsigned a3,
                                      unsigned b0, unsigned b1) {
    asm("mma.sync.aligned.m16n8k16.row.col.f32.f16.f16.f32 "
        "{%0,%1,%2,%3}, {%4,%5,%6,%7}, {%8,%9}, {%0,%1,%2,%3};"
        : "+f"(d[0]), "+f"(d[1]), "+f"(d[2]), "+f"(d[3])
        : "r"(a0), "r"(a1), "r"(a2), "r"(a3), "r"(b0), "r"(b1));
}

// Load k64 x n16 pre-converted B-fragments: 4 coalesced LDG.128.
__device__ __forceinline__ void load_bfrag_pre(int mat, int n16, int lane,
                                               unsigned Bf[4][2][2]) {
    const uint4* src = g_wfrag + ((mat * 4 + n16) * 4) * 32;
#pragma unroll
    for (int cg = 0; cg < 4; ++cg) {
        const uint4 v = __ldg(src + cg * 32 + lane);
        Bf[cg][0][0] = v.x;
        Bf[cg][0][1] = v.y;
        Bf[cg][1][0] = v.z;
        Bf[cg][1][1] = v.w;
    }
}

// ---- prep kernel: convert 6 weight matrices into fp16 fragment order ----
__global__ void prep_kernel(const float* __restrict__ qw, const float* __restrict__ kw,
                            const float* __restrict__ vw, const float* __restrict__ aw,
                            const float* __restrict__ bw, const float* __restrict__ pw)
{
    const int idx = blockIdx.x * blockDim.x + threadIdx.x;   // 0..3071
    if (idx >= 6 * 4 * 4 * 32) return;
    const int lane = idx & 31;
    const int cg   = (idx >> 5) & 3;
    const int n16  = (idx >> 7) & 3;
    const int mat  = idx >> 9;
    const float* W = (mat == 0) ? qw : (mat == 1) ? kw : (mat == 2) ? vw
                   : (mat == 3) ? aw : (mat == 4) ? bw : pw;
    const int g = lane >> 2, tg = lane & 3, n0 = n16 * 16;
    const float* r0 = W + (n0 + g) * 64 + 2 * tg + 16 * cg;
    const float* r1 = W + (n0 + g + 8) * 64 + 2 * tg + 16 * cg;
    uint4 v;
    v.x = packh2(r0[0], r0[1]);
    v.y = packh2(r0[8], r0[9]);
    v.z = packh2(r1[0], r1[1]);
    v.w = packh2(r1[8], r1[9]);
    g_wfrag[idx] = v;
}

__global__ void __launch_bounds__(320, 3) gdn_kernel(
    const float* __restrict__ x,   const float* __restrict__ norm_g,
    const float* __restrict__ qb,  const float* __restrict__ kb,
    const float* __restrict__ vb,  const float* __restrict__ ab,
    const float* __restrict__ bb,  const float* __restrict__ pb,
    const float* __restrict__ qcw, const float* __restrict__ qcb,
    const float* __restrict__ kcw, const float* __restrict__ kcb,
    const float* __restrict__ vcw, const float* __restrict__ vcb,
    const float* __restrict__ png, float* __restrict__ out)
{
    extern __shared__ char smc[];
    float* XF   = (float*)(smc + OFF_XF);
    float* HF   = (float*)(smc + OFF_HF);
    float* BPf  = (float*)(smc + OFF_BP);
    __half* QKVA = (__half*)(smc + OFF_QKVA);

    const int tid  = threadIdx.x;
    const int warp = tid >> 5;
    const int lane = tid & 31;
    const int g    = lane >> 2;
    const int tg   = lane & 3;
    const int sub  = lane >> 4;       // half-warp id
    const int sl   = lane & 15;       // lane within half-warp
    const int b    = blockIdx.x >> 6;
    const int t0   = (blockIdx.x & 63) << 6;
    const long xbase = ((long)b * 4096 + t0) * 64;
    const bool zlo = (t0 == 0), zhi = (t0 + 64 == 4096);

    // ---- x load + zc_rmsnorm -> XF/HF fp16 frags; 16 lanes x 4 ch, 2 rows/iter ----
    {
        const float4 ng4 = *(const float4*)(norm_g + 4 * sl);
        for (int rp = warp; rp < 40; rp += 10) {
            const int r = 2 * rp + sub;
            const int mt = r >> 4, gd = r & 7, hi = (r >> 3) & 1;
            unsigned* xw = (unsigned*)(XF + mt * TSLOTW);
            unsigned* hw = (unsigned*)(HF + mt * TSLOTW);
            const int w0i = frag_word(gd, hi, 4 * sl);
            if (2 * rp >= 66) {          // padding rows 66..79 (warp-uniform branch)
                xw[w0i] = 0u; xw[w0i + 4] = 0u;
                hw[w0i] = 0u; hw[w0i + 4] = 0u;
                continue;
            }
            const int gt = t0 - 1 + r;
            float4 xv = make_float4(0.f, 0.f, 0.f, 0.f);
            if ((unsigned)gt < 4096u)
                xv = *(const float4*)(x + ((long)b * 4096 + gt) * 64 + 4 * sl);
            xw[w0i]     = packh2(xv.x, xv.y);
            xw[w0i + 4] = packh2(xv.z, xv.w);
            float s1 = xv.x + xv.y + xv.z + xv.w;
            float s2 = xv.x * xv.x + xv.y * xv.y + xv.z * xv.z + xv.w * xv.w;
            bfly16_2(s1, s2);
            const float mean = s1 * (1.0f / 64.0f);
            const float var  = s2 * (1.0f / 64.0f) - mean * mean;
            const float inv  = rsqrtf(var + 1e-8f);
            hw[w0i]     = packh2((xv.x - mean) * inv * ng4.x, (xv.y - mean) * inv * ng4.y);
            hw[w0i + 4] = packh2((xv.z - mean) * inv * ng4.z, (xv.w - mean) * inv * ng4.w);
        }
    }
    __syncthreads();

    // ---- phase-1: 20 jobs = (matrix 0..4) x (n16 chunk 0..3); 2 jobs/warp ----
    {
        const float* bsrc[5] = { qb, kb, vb, ab, bb };
#pragma unroll
        for (int jj = 0; jj < 2; ++jj) {
            const int job = warp + 10 * jj;
            const int mat = job >> 2;          // 0..4
            const int n16 = job & 3;
            const int n0  = n16 * 16;
            const float* AF = (mat < 3) ? HF : XF;

            unsigned Bf[4][2][2];
            load_bfrag_pre(mat, n16, lane, Bf);

            float bA[2][2];
#pragma unroll
            for (int nn = 0; nn < 2; ++nn) {
                const float2 bv2 = *(const float2*)(bsrc[mat] + n0 + nn * 8 + 2 * tg);
                bA[nn][0] = bv2.x; bA[nn][1] = bv2.y;
            }

            const bool qkv = (mat < 3);
            __half* Ob = QKVA + mat * (66 * PST);   // valid for mat<4

#pragma unroll
            for (int mt = 0; mt < 5; ++mt) {
                const float4* Afp = (const float4*)(AF + mt * TSLOTW);
                float acc[2][4];
#pragma unroll
                for (int i = 0; i < 2; ++i)
#pragma unroll
                    for (int j = 0; j < 4; ++j) acc[i][j] = 0.f;

#pragma unroll
                for (int c = 0; c < 4; ++c) {
                    const float4 av = Afp[c * 33 + lane];
                    const unsigned a0 = __float_as_uint(av.x);
                    const unsigned a1 = __float_as_uint(av.y);
                    const unsigned a2 = __float_as_uint(av.z);
                    const unsigned a3 = __float_as_uint(av.w);
                    mma16(acc[0], a0, a1, a2, a3, Bf[c][0][0], Bf[c][0][1]);
                    mma16(acc[1], a0, a1, a2, a3, Bf[c][1][0], Bf[c][1][1]);
                }
                const int rA = mt * 16 + g, rB = rA + 8;
#pragma unroll
                for (int nn = 0; nn < 2; ++nn) {
                    const int c0 = n0 + nn * 8 + 2 * tg;
#pragma unroll
                    for (int rr = 0; rr < 2; ++rr) {
                        const int r = rr ? rB : rA;
                        if (r >= 66) continue;
                        float v0 = acc[nn][2 * rr + 0] + bA[nn][0];
                        float v1 = acc[nn][2 * rr + 1] + bA[nn][1];
                        if (qkv && ((zlo && r == 0) || (zhi && r == 65))) { v0 = 0.f; v1 = 0.f; }
                        if (mat < 4) {
                            *(__half2*)(Ob + r * PST + c0) = __floats2half2_rn(v0, v1);
                        } else {
                            *(float2*)(BPf + r * PST + c0) = make_float2(v0, v1);
                        }
                    }
                }
            }
        }
    }
    __syncthreads();

    // ---- per-token stage; channels (2*lane, 2*lane+1), register-carried stencil ----
    // warps 0..3: 7 tokens from s=1+7w; warps 4..9: 6 tokens from s=29+6(w-4)
    {
        const __half* QP = QKVA;
        const __half* KP = QKVA + 66 * PST;
        const __half* VP = QKVA + 2 * 66 * PST;
        const __half* AP = QKVA + 3 * 66 * PST;
        const int s   = (warp < 4) ? (1 + 7 * warp) : (29 + 6 * (warp - 4));
        const int cnt = (warp < 4) ? 7 : 6;
        const int cc0 = 2 * lane;

        // conv params from global (once per warp)
        float cwq[3][2], cwk[3][2], cwv[3][2];
#pragma unroll
        for (int tap = 0; tap < 3; ++tap) {
            cwq[tap][0] = qcw[cc0 * 3 + tap];  cwq[tap][1] = qcw[(cc0 + 1) * 3 + tap];
            cwk[tap][0] = kcw[cc0 * 3 + tap];  cwk[tap][1] = kcw[(cc0 + 1) * 3 + tap];
            cwv[tap][0] = vcw[cc0 * 3 + tap];  cwv[tap][1] = vcw[(cc0 + 1) * 3 + tap];
        }
        const float2 cbq = *(const float2*)(qcb + cc0);
        const float2 cbk = *(const float2*)(kcb + cc0);
        const float2 cbv = *(const float2*)(vcb + cc0);
        const float2 pg2 = *(const float2*)(png + cc0);

        float qm[2], q0[2], km[2], k0[2], vm[2], v0[2];
        {
            const float2 qa = __half22float2(*(const __half2*)(QP + (s - 1) * PST + cc0));
            const float2 qbv = __half22float2(*(const __half2*)(QP + s * PST + cc0));
            const float2 ka = __half22float2(*(const __half2*)(KP + (s - 1) * PST + cc0));
            const float2 kbv = __half22float2(*(const __half2*)(KP + s * PST + cc0));
            const float2 va = __half22float2(*(const __half2*)(VP + (s - 1) * PST + cc0));
            const float2 vbv = __half22float2(*(const __half2*)(VP + s * PST + cc0));
            qm[0] = qa.x; qm[1] = qa.y; q0[0] = qbv.x; q0[1] = qbv.y;
            km[0] = ka.x; km[1] = ka.y; k0[0] = kbv.x; k0[1] = kbv.y;
            vm[0] = va.x; vm[1] = va.y; v0[0] = vbv.x; v0[1] = vbv.y;
        }

        for (int t = s; t < s + cnt; ++t) {
            const float2 qpv = __half22float2(*(const __half2*)(QP + (t + 1) * PST + cc0));
            const float2 kpv = __half22float2(*(const __half2*)(KP + (t + 1) * PST + cc0));
            const float2 vpv = __half22float2(*(const __half2*)(VP + (t + 1) * PST + cc0));
            const float qp[2] = { qpv.x, qpv.y };
            const float kp[2] = { kpv.x, kpv.y };
            const float vp[2] = { vpv.x, vpv.y };
            float qv[2], kv[2], vv[2];
#pragma unroll
            for (int h = 0; h < 2; ++h) {
                qv[h] = sigm(cwq[0][h] * qm[h] + cwq[1][h] * q0[h] + cwq[2][h] * qp[h] + (h ? cbq.y : cbq.x));
                kv[h] = sigm(cwk[0][h] * km[h] + cwk[1][h] * k0[h] + cwk[2][h] * kp[h] + (h ? cbk.y : cbk.x));
                vv[h] = sigm(cwv[0][h] * vm[h] + cwv[1][h] * v0[h] + cwv[2][h] * vp[h] + (h ? cbv.y : cbv.x));
            }
            float qs = qv[0] * qv[0] + qv[1] * qv[1];
            float ks = kv[0] * kv[0] + kv[1] * kv[1];
            wredsum2(qs, ks);
            const float qi = rsqrtf(qs + 1e-8f);
            const float ki = rsqrtf(ks + 1e-8f);
            const float2 av2 = __half22float2(*(const __half2*)(AP + t * PST + cc0));
            const float2 bp2 = *(const float2*)(BPf + t * PST + cc0);
            float d2[2];
            d2[0] = tanh_hw(av2.x) * ((qv[0] * qi) * ((kv[0] * ki) * vv[0])) + bp2.x;
            d2[1] = tanh_hw(av2.y) * ((qv[1] * qi) * ((kv[1] * ki) * vv[1])) + bp2.y;
            float s1 = d2[0] + d2[1], s2 = d2[0] * d2[0] + d2[1] * d2[1];
            wredsum2(s1, s2);
            const float mean = s1 * (1.0f / 64.0f);
            const float var  = s2 * (1.0f / 64.0f) - mean * mean;
            const float inv  = rsqrtf(var + 1e-8f);
            const int tk = t - 1;
            const int mt = tk >> 4, gd = tk & 7, hi = (tk >> 3) & 1;
            frag_store_w(HF + mt * TSLOTW, gd, hi, lane,
                         packh2((d2[0] - mean) * inv * pg2.x, (d2[1] - mean) * inv * pg2.y));
#pragma unroll
            for (int h = 0; h < 2; ++h) {
                qm[h] = q0[h]; q0[h] = qp[h];
                km[h] = k0[h]; k0[h] = kp[h];
                vm[h] = v0[h]; v0[h] = vp[h];
            }
        }
    }
    __syncthreads();

    // ---- final GEMM: 16 jobs m16 x n16 x k64; warps 0..5 do 2 jobs, 6..9 one ----
    for (int job = warp; job < 16; job += 10) {
        const int mt = job >> 2;
        const int n16 = job & 3;
        const int n0 = n16 * 16;

        unsigned Bf[4][2][2];
        load_bfrag_pre(5, n16, lane, Bf);

        const float4* Afp = (const float4*)(HF + mt * TSLOTW);
        float acc[2][4];
#pragma unroll
        for (int i = 0; i < 2; ++i)
#pragma unroll
            for (int j = 0; j < 4; ++j) acc[i][j] = 0.f;

#pragma unroll
        for (int c = 0; c < 4; ++c) {
            const float4 av = Afp[c * 33 + lane];
            mma16(acc[0], __float_as_uint(av.x), __float_as_uint(av.y),
                  __float_as_uint(av.z), __float_as_uint(av.w),
                  Bf[c][0][0], Bf[c][0][1]);
            mma16(acc[1], __float_as_uint(av.x), __float_as_uint(av.y),
                  __float_as_uint(av.z), __float_as_uint(av.w),
                  Bf[c][1][0], Bf[c][1][1]);
        }
#pragma unroll
        for (int nn = 0; nn < 2; ++nn) {
            const int col = n0 + nn * 8 + 2 * tg;
            const float2 pb2 = *(const float2*)(pb + col);
#pragma unroll
            for (int h = 0; h < 2; ++h) {
                const int row = mt * 16 + g + 8 * h;     // token t0 + row
                const float d0 = acc[nn][2 * h + 0] + pb2.x;
                const float d1 = acc[nn][2 * h + 1] + pb2.y;
                const float g0 = sigm(d0 * sigm(d0));
                const float g1 = sigm(d1 * sigm(d1));
                const float2 xv = *(const float2*)(x + xbase + (long)row * 64 + col);
                float2 o = make_float2(xv.x + g0 * d0, xv.y + g1 * d1);
                *(float2*)(out + xbase + (long)row * 64 + col) = o;
            }
        }
    }
}

extern "C" void kernel_launch(void* const* d_in, const int* in_sizes, int n_in,
                              void* d_out, int out_size)
{
    const float* x      = (const float*)d_in[0];
    const float* norm_g = (const float*)d_in[1];
    const float* qw  = (const float*)d_in[2];
    const float* qb  = (const float*)d_in[3];
    const float* kw  = (const float*)d_in[4];
    const float* kb  = (const float*)d_in[5];
    const float* vw  = (const float*)d_in[6];
    const float* vb  = (const float*)d_in[7];
    const float* qcw = (const float*)d_in[8];
    const float* qcb = (const float*)d_in[9];
    const float* kcw = (const float*)d_in[10];
    const float* kcb = (const float*)d_in[11];
    const float* vcw = (const float*)d_in[12];
    const float* vcb = (const float*)d_in[13];
    const float* aw  = (const float*)d_in[14];
    const float* ab  = (const float*)d_in[15];
    const float* bw  = (const float*)d_in[16];
    const float* bb  = (const float*)d_in[17];
    const float* png = (const float*)d_in[18];
    const float* pw  = (const float*)d_in[19];
    const float* pb  = (const float*)d_in[20];
    float* out = (float*)d_out;

    prep_kernel<<<6, 512>>>(qw, kw, vw, aw, bw, pw);

    cudaFuncSetAttribute(gdn_kernel, cudaFuncAttributeMaxDynamicSharedMemorySize, SMEM_BYTES);
    gdn_kernel<<<4096, 320, SMEM_BYTES>>>(
        x, norm_g, qb, kb, vb, ab, bb, pb,
        qcw, qcb, kcw, kcb, vcw, vcb, png, out);
}